// round 1
// baseline (speedup 1.0000x reference)
#include <cuda_runtime.h>
#include <cstdint>

#define NMAX 100000
#define EMAX 1600000
#define FULLMASK 0xffffffffu

// ---------------- scratch (static device allocations; no cudaMalloc) -------
__device__ float g_h0[NMAX * 128];
__device__ float g_hA[NMAX * 128];
__device__ float g_hB[NMAX * 128];
__device__ float g_o0[NMAX * 128];
__device__ float g_o1[NMAX * 128];
__device__ int   g_counts[NMAX];
__device__ int   g_rowptr[NMAX + 1];
__device__ int   g_cursor[NMAX];
__device__ int   g_srcs[EMAX];
__device__ int   g_bsums[256];

// ---------------- dense: out = relu(in @ W + b), W is [128,128] ------------
// Warp computes 4 rows (register blocking R=4 to amortize smem weight reads).
__global__ __launch_bounds__(512, 1) void k_dense_relu(
    const float4* __restrict__ in4, const float* __restrict__ W,
    const float* __restrict__ b, float4* __restrict__ out4, int n)
{
    extern __shared__ float smem[];
    float4* sW = (float4*)smem;            // 128 rows x 32 float4
    float*  sB = smem + 128 * 128;
    for (int i = threadIdx.x; i < 128 * 32; i += blockDim.x)
        sW[i] = ((const float4*)W)[i];
    if (threadIdx.x < 128) sB[threadIdx.x] = b[threadIdx.x];
    __syncthreads();

    const int lane = threadIdx.x & 31;
    const int gw = blockIdx.x * (blockDim.x >> 5) + (threadIdx.x >> 5);
    const int nw = gridDim.x * (blockDim.x >> 5);
    const float bx = sB[lane * 4 + 0], by = sB[lane * 4 + 1];
    const float bz = sB[lane * 4 + 2], bw = sB[lane * 4 + 3];

    for (int base = gw * 4; base < n; base += nw * 4) {
        float4 a[4], o[4];
        #pragma unroll
        for (int r = 0; r < 4; ++r) {
            int node = base + r;
            a[r] = (node < n) ? in4[node * 32 + lane] : make_float4(0.f, 0.f, 0.f, 0.f);
            o[r] = make_float4(bx, by, bz, bw);
        }
        #pragma unroll 2
        for (int kk = 0; kk < 32; ++kk) {
            float4 w0 = sW[(kk * 4 + 0) * 32 + lane];
            float4 w1 = sW[(kk * 4 + 1) * 32 + lane];
            float4 w2 = sW[(kk * 4 + 2) * 32 + lane];
            float4 w3 = sW[(kk * 4 + 3) * 32 + lane];
            #pragma unroll
            for (int r = 0; r < 4; ++r) {
                float a0 = __shfl_sync(FULLMASK, a[r].x, kk);
                float a1 = __shfl_sync(FULLMASK, a[r].y, kk);
                float a2 = __shfl_sync(FULLMASK, a[r].z, kk);
                float a3 = __shfl_sync(FULLMASK, a[r].w, kk);
                o[r].x += a0 * w0.x + a1 * w1.x + a2 * w2.x + a3 * w3.x;
                o[r].y += a0 * w0.y + a1 * w1.y + a2 * w2.y + a3 * w3.y;
                o[r].z += a0 * w0.z + a1 * w1.z + a2 * w2.z + a3 * w3.z;
                o[r].w += a0 * w0.w + a1 * w1.w + a2 * w2.w + a3 * w3.w;
            }
        }
        #pragma unroll
        for (int r = 0; r < 4; ++r) {
            int node = base + r;
            if (node < n) {
                float4 v;
                v.x = fmaxf(o[r].x, 0.f); v.y = fmaxf(o[r].y, 0.f);
                v.z = fmaxf(o[r].z, 0.f); v.w = fmaxf(o[r].w, 0.f);
                out4[node * 32 + lane] = v;
            }
        }
    }
}

// ---------------- fused SAGE layer -----------------------------------------
// Per node i: out = relu( mean_{j in in(i)} h_j @ Wl + bl + h_i @ Wr )
// Warp per node group (R=4): CSR gather (no atomics) + register-blocked GEMM.
__global__ __launch_bounds__(512, 1) void k_sage(
    const float4* __restrict__ hin4, const int* __restrict__ srcs,
    const int* __restrict__ rowptr, const float* __restrict__ Wl,
    const float* __restrict__ blb, const float* __restrict__ Wr,
    float4* __restrict__ hout4, int n)
{
    extern __shared__ float smem[];
    float4* sWl = (float4*)smem;                 // 128x32 float4
    float4* sWr = sWl + 128 * 32;                // 128x32 float4
    float*  sB  = (float*)(sWr + 128 * 32);
    for (int i = threadIdx.x; i < 128 * 32; i += blockDim.x) {
        sWl[i] = ((const float4*)Wl)[i];
        sWr[i] = ((const float4*)Wr)[i];
    }
    if (threadIdx.x < 128) sB[threadIdx.x] = blb[threadIdx.x];
    __syncthreads();

    const int lane = threadIdx.x & 31;
    const int gw = blockIdx.x * (blockDim.x >> 5) + (threadIdx.x >> 5);
    const int nw = gridDim.x * (blockDim.x >> 5);
    const float bx = sB[lane * 4 + 0], by = sB[lane * 4 + 1];
    const float bz = sB[lane * 4 + 2], bw = sB[lane * 4 + 3];

    for (int base = gw * 4; base < n; base += nw * 4) {
        float4 a[4], h[4];
        #pragma unroll
        for (int r = 0; r < 4; ++r) {
            int node = base + r;
            float4 acc = make_float4(0.f, 0.f, 0.f, 0.f);
            if (node < n) {
                int beg = __ldg(&rowptr[node]);
                int end = __ldg(&rowptr[node + 1]);
                int e = beg;
                for (; e + 4 <= end; e += 4) {       // MLP=4 prefetch
                    int s0 = __ldg(&srcs[e + 0]);
                    int s1 = __ldg(&srcs[e + 1]);
                    int s2 = __ldg(&srcs[e + 2]);
                    int s3 = __ldg(&srcs[e + 3]);
                    float4 v0 = __ldg(&hin4[s0 * 32 + lane]);
                    float4 v1 = __ldg(&hin4[s1 * 32 + lane]);
                    float4 v2 = __ldg(&hin4[s2 * 32 + lane]);
                    float4 v3 = __ldg(&hin4[s3 * 32 + lane]);
                    acc.x += (v0.x + v1.x) + (v2.x + v3.x);
                    acc.y += (v0.y + v1.y) + (v2.y + v3.y);
                    acc.z += (v0.z + v1.z) + (v2.z + v3.z);
                    acc.w += (v0.w + v1.w) + (v2.w + v3.w);
                }
                for (; e < end; ++e) {
                    float4 v = __ldg(&hin4[__ldg(&srcs[e]) * 32 + lane]);
                    acc.x += v.x; acc.y += v.y; acc.z += v.z; acc.w += v.w;
                }
                float inv = 1.0f / fmaxf((float)(end - beg), 1.0f);
                acc.x *= inv; acc.y *= inv; acc.z *= inv; acc.w *= inv;
                h[r] = hin4[node * 32 + lane];
            } else {
                h[r] = make_float4(0.f, 0.f, 0.f, 0.f);
            }
            a[r] = acc;
        }
        float4 o[4];
        #pragma unroll
        for (int r = 0; r < 4; ++r) o[r] = make_float4(bx, by, bz, bw);

        #pragma unroll 2
        for (int kk = 0; kk < 32; ++kk) {
            float4 wl0 = sWl[(kk * 4 + 0) * 32 + lane];
            float4 wl1 = sWl[(kk * 4 + 1) * 32 + lane];
            float4 wl2 = sWl[(kk * 4 + 2) * 32 + lane];
            float4 wl3 = sWl[(kk * 4 + 3) * 32 + lane];
            float4 wr0 = sWr[(kk * 4 + 0) * 32 + lane];
            float4 wr1 = sWr[(kk * 4 + 1) * 32 + lane];
            float4 wr2 = sWr[(kk * 4 + 2) * 32 + lane];
            float4 wr3 = sWr[(kk * 4 + 3) * 32 + lane];
            #pragma unroll
            for (int r = 0; r < 4; ++r) {
                float a0 = __shfl_sync(FULLMASK, a[r].x, kk);
                float a1 = __shfl_sync(FULLMASK, a[r].y, kk);
                float a2 = __shfl_sync(FULLMASK, a[r].z, kk);
                float a3 = __shfl_sync(FULLMASK, a[r].w, kk);
                float h0 = __shfl_sync(FULLMASK, h[r].x, kk);
                float h1 = __shfl_sync(FULLMASK, h[r].y, kk);
                float h2 = __shfl_sync(FULLMASK, h[r].z, kk);
                float h3 = __shfl_sync(FULLMASK, h[r].w, kk);
                o[r].x += a0 * wl0.x + a1 * wl1.x + a2 * wl2.x + a3 * wl3.x
                        + h0 * wr0.x + h1 * wr1.x + h2 * wr2.x + h3 * wr3.x;
                o[r].y += a0 * wl0.y + a1 * wl1.y + a2 * wl2.y + a3 * wl3.y
                        + h0 * wr0.y + h1 * wr1.y + h2 * wr2.y + h3 * wr3.y;
                o[r].z += a0 * wl0.z + a1 * wl1.z + a2 * wl2.z + a3 * wl3.z
                        + h0 * wr0.z + h1 * wr1.z + h2 * wr2.z + h3 * wr3.z;
                o[r].w += a0 * wl0.w + a1 * wl1.w + a2 * wl2.w + a3 * wl3.w
                        + h0 * wr0.w + h1 * wr1.w + h2 * wr2.w + h3 * wr3.w;
            }
        }
        #pragma unroll
        for (int r = 0; r < 4; ++r) {
            int node = base + r;
            if (node < n) {
                float4 v;
                v.x = fmaxf(o[r].x, 0.f); v.y = fmaxf(o[r].y, 0.f);
                v.z = fmaxf(o[r].z, 0.f); v.w = fmaxf(o[r].w, 0.f);
                hout4[node * 32 + lane] = v;
            }
        }
    }
}

// ---------------- CSR build -------------------------------------------------
__global__ void k_count(const int* __restrict__ ed, int* __restrict__ counts, int E)
{
    int i = blockIdx.x * blockDim.x + threadIdx.x;
    if (i < E) atomicAdd(&counts[ed[E + i]], 1);
}

__global__ void k_scan1(const int* __restrict__ counts, int* __restrict__ rowptr,
                        int* __restrict__ bsums, int n)
{
    __shared__ int s[1024];
    int i = blockIdx.x * 1024 + threadIdx.x;
    int v = (i < n) ? counts[i] : 0;
    s[threadIdx.x] = v;
    __syncthreads();
    #pragma unroll
    for (int off = 1; off < 1024; off <<= 1) {
        int t = (threadIdx.x >= off) ? s[threadIdx.x - off] : 0;
        __syncthreads();
        s[threadIdx.x] += t;
        __syncthreads();
    }
    if (i < n) rowptr[i] = s[threadIdx.x] - v;   // block-local exclusive
    if (threadIdx.x == 1023) bsums[blockIdx.x] = s[1023];
}

__global__ void k_scan2(int* __restrict__ bsums, int nb, int* __restrict__ rowptr, int n)
{
    if (threadIdx.x == 0 && blockIdx.x == 0) {
        int run = 0;
        for (int b = 0; b < nb; ++b) { int t = bsums[b]; bsums[b] = run; run += t; }
        rowptr[n] = run;
    }
}

__global__ void k_scan3(int* __restrict__ rowptr, const int* __restrict__ bsums,
                        int* __restrict__ cursor, int n)
{
    int i = blockIdx.x * 1024 + threadIdx.x;
    if (i < n) {
        int v = rowptr[i] + bsums[blockIdx.x];
        rowptr[i] = v;
        cursor[i] = v;
    }
}

__global__ void k_scatter(const int* __restrict__ ed, int* __restrict__ cursor,
                          int* __restrict__ srcs, int E)
{
    int i = blockIdx.x * blockDim.x + threadIdx.x;
    if (i < E) {
        int d = ed[E + i];
        int p = atomicAdd(&cursor[d], 1);
        srcs[p] = ed[i];
    }
}

// ---------------- attention combine ----------------------------------------
__global__ __launch_bounds__(256) void k_att(
    const float4* __restrict__ o0, const float4* __restrict__ o1,
    const float* __restrict__ watt, const float* __restrict__ batt,
    float4* __restrict__ agg, int n)
{
    const int lane = threadIdx.x & 31;
    const int gw = blockIdx.x * (blockDim.x >> 5) + (threadIdx.x >> 5);
    const int nw = gridDim.x * (blockDim.x >> 5);
    const int k0 = lane * 4;
    // hoist per-lane attention weights (constant across nodes)
    float wa0[4], wa1[4], wb0[4], wb1[4];
    #pragma unroll
    for (int c = 0; c < 4; ++c) {
        wa0[c] = __ldg(&watt[(k0 + c) * 2 + 0]);
        wa1[c] = __ldg(&watt[(k0 + c) * 2 + 1]);
        wb0[c] = __ldg(&watt[(128 + k0 + c) * 2 + 0]);
        wb1[c] = __ldg(&watt[(128 + k0 + c) * 2 + 1]);
    }
    const float bt0 = __ldg(&batt[0]), bt1 = __ldg(&batt[1]);

    for (int node = gw; node < n; node += nw) {
        float4 a = o0[node * 32 + lane];
        float4 b = o1[node * 32 + lane];
        float p0 = a.x * wa0[0] + a.y * wa0[1] + a.z * wa0[2] + a.w * wa0[3]
                 + b.x * wb0[0] + b.y * wb0[1] + b.z * wb0[2] + b.w * wb0[3];
        float p1 = a.x * wa1[0] + a.y * wa1[1] + a.z * wa1[2] + a.w * wa1[3]
                 + b.x * wb1[0] + b.y * wb1[1] + b.z * wb1[2] + b.w * wb1[3];
        #pragma unroll
        for (int off = 16; off; off >>= 1) {
            p0 += __shfl_xor_sync(FULLMASK, p0, off);
            p1 += __shfl_xor_sync(FULLMASK, p1, off);
        }
        float z0 = p0 + bt0, z1 = p1 + bt1;
        float m = fmaxf(z0, z1);
        float e0 = expf(z0 - m), e1 = expf(z1 - m);
        float inv = 1.0f / (e0 + e1);
        float a0 = e0 * inv, a1 = e1 * inv;
        float4 r;
        r.x = a0 * a.x + a1 * b.x;
        r.y = a0 * a.y + a1 * b.y;
        r.z = a0 * a.z + a1 * b.z;
        r.w = a0 * a.w + a1 * b.w;
        agg[node * 32 + lane] = r;
    }
}

// ---------------- classifier + pattern heads -------------------------------
__global__ __launch_bounds__(256) void k_heads(
    const float4* __restrict__ agg,
    const float* __restrict__ wc1, const float* __restrict__ bc1,
    const float* __restrict__ wc2, const float* __restrict__ bc2,
    const float* __restrict__ wp1, const float* __restrict__ bp1,
    const float* __restrict__ wp2, const float* __restrict__ bp2,
    float* __restrict__ fraud, float* __restrict__ pat, int n)
{
    extern __shared__ float sm[];
    float* sC1 = sm;              // 128*64
    float* sP1 = sC1 + 8192;      // 128*64
    float* sC2 = sP1 + 8192;      // 64*2
    float* sP2 = sC2 + 128;       // 64*5
    float* sBC1 = sP2 + 320;      // 64
    float* sBP1 = sBC1 + 64;      // 64
    float* sBC2 = sBP1 + 64;      // 2
    float* sBP2 = sBC2 + 2;       // 5
    for (int i = threadIdx.x; i < 8192; i += blockDim.x) { sC1[i] = wc1[i]; sP1[i] = wp1[i]; }
    for (int i = threadIdx.x; i < 128;  i += blockDim.x) sC2[i] = wc2[i];
    for (int i = threadIdx.x; i < 320;  i += blockDim.x) sP2[i] = wp2[i];
    for (int i = threadIdx.x; i < 64;   i += blockDim.x) { sBC1[i] = bc1[i]; sBP1[i] = bp1[i]; }
    if (threadIdx.x < 2) sBC2[threadIdx.x] = bc2[threadIdx.x];
    if (threadIdx.x < 5) sBP2[threadIdx.x] = bp2[threadIdx.x];
    __syncthreads();

    const int lane = threadIdx.x & 31;
    const int gw = blockIdx.x * (blockDim.x >> 5) + (threadIdx.x >> 5);
    const int nw = gridDim.x * (blockDim.x >> 5);
    const float2* sC1v = (const float2*)sC1;
    const float2* sP1v = (const float2*)sP1;

    // hoist per-lane second-layer weights and biases
    const int hA = 2 * lane, hBb = 2 * lane + 1;
    const float c2a0 = sC2[hA * 2 + 0], c2a1 = sC2[hA * 2 + 1];
    const float c2b0 = sC2[hBb * 2 + 0], c2b1 = sC2[hBb * 2 + 1];
    float p2a[5], p2b[5];
    #pragma unroll
    for (int j = 0; j < 5; ++j) { p2a[j] = sP2[hA * 5 + j]; p2b[j] = sP2[hBb * 5 + j]; }
    const float bC1a = sBC1[hA], bC1b = sBC1[hBb];
    const float bP1a = sBP1[hA], bP1b = sBP1[hBb];
    const float bC2_0 = sBC2[0], bC2_1 = sBC2[1];
    float bP2v[5];
    #pragma unroll
    for (int j = 0; j < 5; ++j) bP2v[j] = sBP2[j];

    for (int node = gw; node < n; node += nw) {
        float4 ar = agg[node * 32 + lane];
        float hc0 = bC1a, hc1 = bC1b, hp0 = bP1a, hp1 = bP1b;
        #pragma unroll 4
        for (int kk = 0; kk < 32; ++kk) {
            float av[4];
            av[0] = __shfl_sync(FULLMASK, ar.x, kk);
            av[1] = __shfl_sync(FULLMASK, ar.y, kk);
            av[2] = __shfl_sync(FULLMASK, ar.z, kk);
            av[3] = __shfl_sync(FULLMASK, ar.w, kk);
            #pragma unroll
            for (int j = 0; j < 4; ++j) {
                int k = kk * 4 + j;
                float2 wc = sC1v[k * 32 + lane];
                float2 wp = sP1v[k * 32 + lane];
                hc0 += av[j] * wc.x; hc1 += av[j] * wc.y;
                hp0 += av[j] * wp.x; hp1 += av[j] * wp.y;
            }
        }
        hc0 = fmaxf(hc0, 0.f); hc1 = fmaxf(hc1, 0.f);
        hp0 = fmaxf(hp0, 0.f); hp1 = fmaxf(hp1, 0.f);

        float f0 = hc0 * c2a0 + hc1 * c2b0;
        float f1 = hc0 * c2a1 + hc1 * c2b1;
        float q[5];
        #pragma unroll
        for (int j = 0; j < 5; ++j) q[j] = hp0 * p2a[j] + hp1 * p2b[j];
        #pragma unroll
        for (int off = 16; off; off >>= 1) {
            f0 += __shfl_xor_sync(FULLMASK, f0, off);
            f1 += __shfl_xor_sync(FULLMASK, f1, off);
            #pragma unroll
            for (int j = 0; j < 5; ++j) q[j] += __shfl_xor_sync(FULLMASK, q[j], off);
        }
        if (lane == 0) {
            fraud[node * 2 + 0] = f0 + bC2_0;
            fraud[node * 2 + 1] = f1 + bC2_1;
            #pragma unroll
            for (int j = 0; j < 5; ++j) pat[node * 5 + j] = q[j] + bP2v[j];
        }
    }
}

// ---------------- launcher --------------------------------------------------
extern "C" void kernel_launch(void* const* d_in, const int* in_sizes, int n_in,
                              void* d_out, int out_size)
{
    const float* x     = (const float*)d_in[0];
    const int*   e0    = (const int*)  d_in[1];
    const int*   e1    = (const int*)  d_in[2];
    const float* w_emb = (const float*)d_in[3];
    const float* b_emb = (const float*)d_in[4];
    const float* Wl    = (const float*)d_in[5];
    const float* bl    = (const float*)d_in[6];
    const float* Wr    = (const float*)d_in[7];
    const float* w_att = (const float*)d_in[8];
    const float* b_att = (const float*)d_in[9];
    const float* w_c1  = (const float*)d_in[10];
    const float* b_c1  = (const float*)d_in[11];
    const float* w_c2  = (const float*)d_in[12];
    const float* b_c2  = (const float*)d_in[13];
    const float* w_p1  = (const float*)d_in[14];
    const float* b_p1  = (const float*)d_in[15];
    const float* w_p2  = (const float*)d_in[16];
    const float* b_p2  = (const float*)d_in[17];

    int n = in_sizes[0] / 128; if (n > NMAX) n = NMAX;
    int E = in_sizes[1] / 2;   if (E > EMAX) E = EMAX;

    float* out_fraud = (float*)d_out;
    float* out_pat   = out_fraud + (size_t)n * 2;
    float* out_agg   = out_pat   + (size_t)n * 5;

    float *h0, *hA, *hB, *o0, *o1;
    int *counts, *rowptr, *cursor, *srcs, *bsums;
    cudaGetSymbolAddress((void**)&h0, g_h0);
    cudaGetSymbolAddress((void**)&hA, g_hA);
    cudaGetSymbolAddress((void**)&hB, g_hB);
    cudaGetSymbolAddress((void**)&o0, g_o0);
    cudaGetSymbolAddress((void**)&o1, g_o1);
    cudaGetSymbolAddress((void**)&counts, g_counts);
    cudaGetSymbolAddress((void**)&rowptr, g_rowptr);
    cudaGetSymbolAddress((void**)&cursor, g_cursor);
    cudaGetSymbolAddress((void**)&srcs, g_srcs);
    cudaGetSymbolAddress((void**)&bsums, g_bsums);

    const int SM_DENSE = (128 * 128 + 128) * 4;
    const int SM_SAGE  = (2 * 128 * 128 + 128) * 4;
    const int SM_HEADS = (8192 + 8192 + 128 + 320 + 64 + 64 + 2 + 5) * 4;
    cudaFuncSetAttribute(k_dense_relu, cudaFuncAttributeMaxDynamicSharedMemorySize, SM_DENSE);
    cudaFuncSetAttribute(k_sage,       cudaFuncAttributeMaxDynamicSharedMemorySize, SM_SAGE);
    cudaFuncSetAttribute(k_heads,      cudaFuncAttributeMaxDynamicSharedMemorySize, SM_HEADS);

    // node embedding
    k_dense_relu<<<296, 512, SM_DENSE>>>((const float4*)x, w_emb, b_emb, (float4*)h0, n);

    const int NB = (n + 1023) / 1024;
    for (int et = 0; et < 2; ++et) {
        const int* ed = et ? e1 : e0;
        cudaMemsetAsync(counts, 0, n * sizeof(int));
        k_count<<<(E + 255) / 256, 256>>>(ed, counts, E);
        k_scan1<<<NB, 1024>>>(counts, rowptr, bsums, n);
        k_scan2<<<1, 32>>>(bsums, NB, rowptr, n);
        k_scan3<<<NB, 1024>>>(rowptr, bsums, cursor, n);
        k_scatter<<<(E + 255) / 256, 256>>>(ed, cursor, srcs, E);

        const float* hin = h0;
        float* outs[3] = { hA, hB, et ? o1 : o0 };
        for (int l = 0; l < 3; ++l) {
            const float* Wlp = Wl + (size_t)(et * 3 + l) * 128 * 128;
            const float* blp = bl + (size_t)(et * 3 + l) * 128;
            const float* Wrp = Wr + (size_t)(et * 3 + l) * 128 * 128;
            k_sage<<<148, 512, SM_SAGE>>>((const float4*)hin, srcs, rowptr,
                                          Wlp, blp, Wrp, (float4*)outs[l], n);
            hin = outs[l];
        }
    }

    k_att<<<1024, 256>>>((const float4*)o0, (const float4*)o1, w_att, b_att,
                         (float4*)out_agg, n);
    k_heads<<<592, 256, SM_HEADS>>>((const float4*)out_agg,
                                    w_c1, b_c1, w_c2, b_c2,
                                    w_p1, b_p1, w_p2, b_p2,
                                    out_fraud, out_pat, n);
}